// round 2
// baseline (speedup 1.0000x reference)
#include <cuda_runtime.h>
#include <cuda_bf16.h>

// masked ragged mean: input[B=64, L=4096, D=256] fp32, length[B] -> out[B, D]
#define BB 64
#define LL 4096
#define DD 256
#define SPLITS 32                 // L-chunks per batch -> 64*32 = 2048 CTAs
#define CHUNK (LL / SPLITS)       // 128 rows per CTA
#define D4 (DD / 4)               // 64 float4 per row

// chunk partials + per-batch arrival counters (module-load zero-initialized;
// the finishing block resets its counter so graph replays stay correct)
__device__ float g_scratch[BB][SPLITS][DD];   // 2 MB
__device__ int   g_count[BB];

// length may arrive as int64 (reference declares int64) or int32 (JAX x64 off).
// As int64, element 0 is <= LL only in the true int64 layout; an int32 layout
// packs the next (>=1) length into the high word, making the probe >= 2^32.
__device__ __forceinline__ long long load_len(const void* lp, int b) {
    const long long probe = ((const long long*)lp)[0];
    if (probe >= 1 && probe <= (long long)LL)
        return ((const long long*)lp)[b];
    return (long long)((const int*)lp)[b];
}

__global__ void __launch_bounds__(256) avg_fused_kernel(
    const float* __restrict__ in, const void* __restrict__ lenp,
    float* __restrict__ out)
{
    const int b     = blockIdx.x;       // batch
    const int chunk = blockIdx.y;       // L-chunk
    const int tid   = threadIdx.x;      // 256 threads

    const long long lb = load_len(lenp, b);
    const int len      = (int)lb;
    const int n_active = (len + CHUNK - 1) / CHUNK;
    if (chunk >= n_active) return;       // uniform per block

    const int start = chunk * CHUNK;
    int end = start + CHUNK;
    if (end > len) end = len;

    const int d4 = tid & (D4 - 1);       // float4 column 0..63
    const int r  = tid >> 6;             // row-lane 0..3

    const float4* __restrict__ base =
        (const float4*)(in + (size_t)b * LL * DD) + d4;

    float4 acc = make_float4(0.f, 0.f, 0.f, 0.f);

    int l = start + r;
    #pragma unroll 1
    for (; l + 12 < end; l += 16) {       // 4 independent 16B loads in flight
        float4 v0 = base[(size_t)(l     ) * D4];
        float4 v1 = base[(size_t)(l +  4) * D4];
        float4 v2 = base[(size_t)(l +  8) * D4];
        float4 v3 = base[(size_t)(l + 12) * D4];
        acc.x += v0.x + v1.x + v2.x + v3.x;
        acc.y += v0.y + v1.y + v2.y + v3.y;
        acc.z += v0.z + v1.z + v2.z + v3.z;
        acc.w += v0.w + v1.w + v2.w + v3.w;
    }
    for (; l < end; l += 4) {
        float4 v = base[(size_t)l * D4];
        acc.x += v.x; acc.y += v.y; acc.z += v.z; acc.w += v.w;
    }

    // intra-block reduce across the 4 row-lanes
    __shared__ float4 sm[256];
    sm[tid] = acc;
    __syncthreads();

    if (r == 0) {
        float4 a0 = sm[d4];
        float4 a1 = sm[d4 + 64];
        float4 a2 = sm[d4 + 128];
        float4 a3 = sm[d4 + 192];
        float4 s;
        s.x = (a0.x + a1.x) + (a2.x + a3.x);
        s.y = (a0.y + a1.y) + (a2.y + a3.y);
        s.z = (a0.z + a1.z) + (a2.z + a3.z);
        s.w = (a0.w + a1.w) + (a2.w + a3.w);
        // publish chunk partial, bypassing L1
        __stcg((float4*)&g_scratch[b][chunk][d4 * 4], s);
    }

    // stores -> fence -> sync -> arrival atomic (threadFenceReduction pattern)
    __threadfence();
    __syncthreads();

    __shared__ int isLast;
    if (tid == 0) {
        int v = atomicAdd(&g_count[b], 1);
        isLast = (v == n_active - 1);
        if (isLast) g_count[b] = 0;       // reset for next graph replay
    }
    __syncthreads();
    if (!isLast) return;

    __threadfence();                      // acquire side

    // deterministic final reduce: fixed chunk order, thread tid owns column tid
    float s = 0.0f;
    for (int c = 0; c < n_active; c++)
        s += __ldcg(&g_scratch[b][c][tid]);

    out[b * DD + tid] = s * (1.0f / (float)len);
}

extern "C" void kernel_launch(void* const* d_in, const int* in_sizes, int n_in,
                              void* d_out, int out_size) {
    const float* in   = (const float*)d_in[0];
    const void*  lenp = d_in[1];
    float* out = (float*)d_out;

    avg_fused_kernel<<<dim3(BB, SPLITS), 256>>>(in, lenp, out);
}